// round 3
// baseline (speedup 1.0000x reference)
#include <cuda_runtime.h>
#include <math.h>

// Problem constants (fixed by setup_inputs)
#define B_  2
#define T_  2048
#define C_  1024
#define H_  16
#define D_  64
#define BT_ (B_*T_)          // 4096

// Scratch (allocation-free rule: __device__ globals)
__device__ float g_q[BT_*C_];
__device__ float g_k[BT_*C_];
__device__ float g_v[BT_*C_];
__device__ float g_attn[BT_*C_];

// ---------------------------------------------------------------------------
// SGEMM (NT): C[m,n] = sum_k A[m,k] * W[n,k]
// Both operands K-contiguous (row-major x, row-major W). Tile 128x64x16,
// 256 threads, 8x4 per-thread microtile, float4 smem reads.
// M,N,K assumed multiples of 128/64/16 (4096,1024,1024 here).
// ---------------------------------------------------------------------------
__global__ __launch_bounds__(256) void sgemm_nt(
    const float* __restrict__ A, const float* __restrict__ W,
    float* __restrict__ Cout, int M, int N, int K)
{
    __shared__ float As[16][128];   // As[k][m]
    __shared__ float Bs[16][64];    // Bs[k][n]

    const int tid = threadIdx.x;
    const int tx = tid & 15;        // n-group
    const int ty = tid >> 4;        // m-group
    const int row0 = blockIdx.y << 7;
    const int col0 = blockIdx.x << 6;

    float acc[8][4];
    #pragma unroll
    for (int i = 0; i < 8; ++i)
        #pragma unroll
        for (int j = 0; j < 4; ++j) acc[i][j] = 0.f;

    for (int k0 = 0; k0 < K; k0 += 16) {
        // Load A tile: 128 rows x 16 cols = 512 float4
        #pragma unroll
        for (int li = tid; li < 512; li += 256) {
            int ar = li >> 2;
            int ac = (li & 3) << 2;
            float4 v = *(const float4*)(A + (size_t)(row0 + ar) * K + k0 + ac);
            As[ac + 0][ar] = v.x;
            As[ac + 1][ar] = v.y;
            As[ac + 2][ar] = v.z;
            As[ac + 3][ar] = v.w;
        }
        // Load W tile: 64 rows x 16 cols = 256 float4 (one per thread)
        {
            int br = tid >> 2;
            int bc = (tid & 3) << 2;
            float4 v = *(const float4*)(W + (size_t)(col0 + br) * K + k0 + bc);
            Bs[bc + 0][br] = v.x;
            Bs[bc + 1][br] = v.y;
            Bs[bc + 2][br] = v.z;
            Bs[bc + 3][br] = v.w;
        }
        __syncthreads();

        #pragma unroll
        for (int k = 0; k < 16; ++k) {
            float4 a0 = *(const float4*)&As[k][(ty << 3)];
            float4 a1 = *(const float4*)&As[k][(ty << 3) + 4];
            float4 b0 = *(const float4*)&Bs[k][(tx << 2)];
            float a[8] = {a0.x, a0.y, a0.z, a0.w, a1.x, a1.y, a1.z, a1.w};
            float b[4] = {b0.x, b0.y, b0.z, b0.w};
            #pragma unroll
            for (int i = 0; i < 8; ++i)
                #pragma unroll
                for (int j = 0; j < 4; ++j)
                    acc[i][j] += a[i] * b[j];
        }
        __syncthreads();
    }

    #pragma unroll
    for (int i = 0; i < 8; ++i) {
        float4 v = make_float4(acc[i][0], acc[i][1], acc[i][2], acc[i][3]);
        *(float4*)(Cout + (size_t)(row0 + (ty << 3) + i) * N + col0 + (tx << 2)) = v;
    }
}

// ---------------------------------------------------------------------------
// RoPE in-place on Q and K, [B,T,C] layout, per-head dim D=64, half=32.
// q'[d]      = q[d]*cos(a) - q[d+32]*sin(a)
// q'[d+32]   = q[d+32]*cos(a) + q[d]*sin(a),  a = t * 10000^{-(2d)/D}
// ---------------------------------------------------------------------------
__global__ void rope_kernel(float* __restrict__ q, float* __restrict__ k)
{
    int idx = blockIdx.x * blockDim.x + threadIdx.x;   // [b][t][h][i<32]
    int i = idx & 31;
    int h = (idx >> 5) & 15;
    int t = (idx >> 9) & 2047;
    int b = idx >> 20;

    float inv = powf(10000.0f, -(float)(2 * i) / (float)D_);
    float ang = (float)t * inv;
    float s, c;
    sincosf(ang, &s, &c);

    size_t base = ((size_t)(b * T_ + t)) * C_ + h * D_ + i;
    float x1 = q[base], x2 = q[base + 32];
    q[base]      = x1 * c - x2 * s;
    q[base + 32] = x2 * c + x1 * s;
    x1 = k[base]; x2 = k[base + 32];
    k[base]      = x1 * c - x2 * s;
    k[base + 32] = x2 * c + x1 * s;
}

// ---------------------------------------------------------------------------
// Causal flash attention, fp32, online softmax.
// Grid: (T/64 query tiles, B*H). 256 threads as 16x16; each thread owns a
// 4x4 microtile of S / P / O. D = 64. P overwrites K smem tile.
// Row reductions via 16-lane butterfly shuffles (lanes with equal ty are a
// contiguous warp half).
// ---------------------------------------------------------------------------
#define FA_PAD 65
#define FA_SMEM (3 * 64 * FA_PAD * (int)sizeof(float))

__global__ __launch_bounds__(256) void flash_attn(
    const float* __restrict__ q, const float* __restrict__ k,
    const float* __restrict__ v, float* __restrict__ o)
{
    extern __shared__ float sm[];
    float* Qs  = sm;                  // [64][65]
    float* KPs = sm + 64 * FA_PAD;    // [64][65]  K tile, then P tile
    float* Vs  = sm + 2 * 64 * FA_PAD;// [64][65]

    const int tid = threadIdx.x;
    const int tx = tid & 15;
    const int ty = tid >> 4;
    const int qblk = blockIdx.x;
    const int bh = blockIdx.y;
    const int b = bh >> 4, h = bh & 15;
    const int i0 = qblk << 6;

    const float* qb = q + ((size_t)b * T_) * C_ + h * D_;
    const float* kb = k + ((size_t)b * T_) * C_ + h * D_;
    const float* vb = v + ((size_t)b * T_) * C_ + h * D_;

    for (int idx = tid; idx < 64 * 64; idx += 256) {
        int r = idx >> 6, c = idx & 63;
        Qs[r * FA_PAD + c] = qb[(size_t)(i0 + r) * C_ + c];
    }

    float acc[4][4];
    float m_i[4], l_i[4];
    #pragma unroll
    for (int i = 0; i < 4; ++i) {
        m_i[i] = -1e30f; l_i[i] = 0.f;
        #pragma unroll
        for (int j = 0; j < 4; ++j) acc[i][j] = 0.f;
    }
    const int r0 = ty << 2, c0 = tx << 2;
    __syncthreads();

    for (int j = 0; j <= qblk; ++j) {
        for (int idx = tid; idx < 64 * 64; idx += 256) {
            int r = idx >> 6, c = idx & 63;
            KPs[r * FA_PAD + c] = kb[(size_t)((j << 6) + r) * C_ + c];
            Vs [r * FA_PAD + c] = vb[(size_t)((j << 6) + r) * C_ + c];
        }
        __syncthreads();

        // S = Q K^T (thread 4x4)
        float s[4][4];
        #pragma unroll
        for (int i = 0; i < 4; ++i)
            #pragma unroll
            for (int jj = 0; jj < 4; ++jj) s[i][jj] = 0.f;

        #pragma unroll 8
        for (int kk = 0; kk < 64; ++kk) {
            float qv[4], kv[4];
            #pragma unroll
            for (int i = 0; i < 4; ++i) qv[i] = Qs[(r0 + i) * FA_PAD + kk];
            #pragma unroll
            for (int i = 0; i < 4; ++i) kv[i] = KPs[(c0 + i) * FA_PAD + kk];
            #pragma unroll
            for (int i = 0; i < 4; ++i)
                #pragma unroll
                for (int jj = 0; jj < 4; ++jj)
                    s[i][jj] += qv[i] * kv[jj];
        }
        __syncthreads();   // done reading K tile; P overwrites it

        // Online softmax per row
        #pragma unroll
        for (int i = 0; i < 4; ++i) {
            int grow = i0 + r0 + i;
            float sv[4];
            float mx = -1e30f;
            #pragma unroll
            for (int jj = 0; jj < 4; ++jj) {
                int gcol = (j << 6) + c0 + jj;
                float val = s[i][jj] * 0.125f;   // 1/sqrt(64)
                if (gcol > grow) val = -1e30f;
                sv[jj] = val;
                mx = fmaxf(mx, val);
            }
            #pragma unroll
            for (int off = 1; off < 16; off <<= 1)
                mx = fmaxf(mx, __shfl_xor_sync(0xffffffffu, mx, off));
            float m_new = fmaxf(m_i[i], mx);
            float scale = __expf(m_i[i] - m_new);
            float rs = 0.f;
            #pragma unroll
            for (int jj = 0; jj < 4; ++jj) {
                float p = __expf(sv[jj] - m_new);
                sv[jj] = p;
                rs += p;
            }
            #pragma unroll
            for (int off = 1; off < 16; off <<= 1)
                rs += __shfl_xor_sync(0xffffffffu, rs, off);
            l_i[i] = l_i[i] * scale + rs;
            m_i[i] = m_new;
            #pragma unroll
            for (int jj = 0; jj < 4; ++jj) acc[i][jj] *= scale;
            #pragma unroll
            for (int jj = 0; jj < 4; ++jj)
                KPs[(r0 + i) * FA_PAD + c0 + jj] = sv[jj];
        }
        __syncthreads();

        // O += P @ V
        #pragma unroll 8
        for (int ss = 0; ss < 64; ++ss) {
            float pv[4], vv[4];
            #pragma unroll
            for (int i = 0; i < 4; ++i) pv[i] = KPs[(r0 + i) * FA_PAD + ss];
            #pragma unroll
            for (int jj = 0; jj < 4; ++jj) vv[jj] = Vs[ss * FA_PAD + c0 + jj];
            #pragma unroll
            for (int i = 0; i < 4; ++i)
                #pragma unroll
                for (int jj = 0; jj < 4; ++jj)
                    acc[i][jj] += pv[i] * vv[jj];
        }
        __syncthreads();
    }

    float* ob = o + ((size_t)b * T_) * C_ + h * D_;
    #pragma unroll
    for (int i = 0; i < 4; ++i) {
        float inv_l = 1.f / l_i[i];
        #pragma unroll
        for (int jj = 0; jj < 4; ++jj)
            ob[(size_t)(i0 + r0 + i) * C_ + c0 + jj] = acc[i][jj] * inv_l;
    }
}

// ---------------------------------------------------------------------------
// Launch: 3 projections -> RoPE -> flash attention -> output projection
// ---------------------------------------------------------------------------
extern "C" void kernel_launch(void* const* d_in, const int* in_sizes, int n_in,
                              void* d_out, int out_size)
{
    const float* x  = (const float*)d_in[0];
    const float* Wq = (const float*)d_in[1];
    const float* Wk = (const float*)d_in[2];
    const float* Wv = (const float*)d_in[3];
    const float* Wo = (const float*)d_in[4];
    float* out = (float*)d_out;

    float *qp, *kp, *vp, *ap;
    cudaGetSymbolAddress((void**)&qp, g_q);
    cudaGetSymbolAddress((void**)&kp, g_k);
    cudaGetSymbolAddress((void**)&vp, g_v);
    cudaGetSymbolAddress((void**)&ap, g_attn);

    dim3 gemm_grid(C_ / 64, BT_ / 128);

    sgemm_nt<<<gemm_grid, 256>>>(x, Wq, qp, BT_, C_, C_);
    sgemm_nt<<<gemm_grid, 256>>>(x, Wk, kp, BT_, C_, C_);
    sgemm_nt<<<gemm_grid, 256>>>(x, Wv, vp, BT_, C_, C_);

    rope_kernel<<<(B_ * T_ * H_ * (D_ / 2)) / 256, 256>>>(qp, kp);

    cudaFuncSetAttribute((const void*)flash_attn,
                         cudaFuncAttributeMaxDynamicSharedMemorySize, FA_SMEM);
    flash_attn<<<dim3(T_ / 64, B_ * H_), 256, FA_SMEM>>>(qp, kp, vp, ap);

    sgemm_nt<<<gemm_grid, 256>>>(ap, Wo, out, BT_, C_, C_);
}

// round 5
// speedup vs baseline: 1.7824x; 1.7824x over previous
#include <cuda_runtime.h>
#include <math.h>
#include <stdint.h>

// Problem constants (fixed by setup_inputs)
#define B_  2
#define T_  2048
#define C_  1024
#define H_  16
#define D_  64
#define BT_ (B_*T_)          // 4096

// Scratch (allocation-free rule: __device__ globals)
__device__ float g_q[BT_*C_];
__device__ float g_k[BT_*C_];
__device__ float g_v[BT_*C_];
__device__ float g_attn[BT_*C_];
__device__ float g_xr[BT_*C_];      // tf32-rounded x
__device__ float g_wq[C_*C_];
__device__ float g_wk[C_*C_];
__device__ float g_wv[C_*C_];
__device__ float g_wo[C_*C_];

// ===========================================================================
// Helpers
// ===========================================================================
__device__ __forceinline__ uint32_t smem_u32(const void* p) {
    uint32_t a;
    asm("{ .reg .u64 t; cvta.to.shared.u64 t, %1; cvt.u32.u64 %0, t; }"
        : "=r"(a) : "l"(p));
    return a;
}
__device__ __forceinline__ void cp_async16(uint32_t saddr, const void* gaddr) {
    asm volatile("cp.async.ca.shared.global [%0], [%1], 16;"
                 :: "r"(saddr), "l"(gaddr) : "memory");
}
__device__ __forceinline__ void cp_commit() {
    asm volatile("cp.async.commit_group;" ::: "memory");
}
template<int N>
__device__ __forceinline__ void cp_wait() {
    asm volatile("cp.async.wait_group %0;" :: "n"(N) : "memory");
}
// tf32 mma: D = A(16x8) * B(8x8) + D   (row.col)
__device__ __forceinline__ void mma_tf32(float* c, const uint32_t* a, const uint32_t* b) {
    asm volatile(
        "mma.sync.aligned.m16n8k8.row.col.f32.tf32.tf32.f32 "
        "{%0,%1,%2,%3}, {%4,%5,%6,%7}, {%8,%9}, {%0,%1,%2,%3};"
        : "+f"(c[0]), "+f"(c[1]), "+f"(c[2]), "+f"(c[3])
        : "r"(a[0]), "r"(a[1]), "r"(a[2]), "r"(a[3]), "r"(b[0]), "r"(b[1]));
}

// ===========================================================================
// tf32 tensor-core GEMM (NT): C[m,n] = sum_k A[m,k] * W[n,k]
// CTA 128x128, K-chunk 32, 2-stage cp.async pipeline, 256 threads (8 warps,
// 2x4 grid, warp tile 64x32, 4x4 m16n8k8 per warp per k-step).
// Smem rows padded to 36 floats -> all fragment LDS are bank-conflict-free.
// M,N,K multiples of 128/128/32.
// ===========================================================================
#define GK      32
#define GSTRIDE 36
#define G_TILE  (128 * GSTRIDE)          // floats per matrix per stage
#define G_STAGE (2 * G_TILE)             // A + B
#define G_SMEM  (2 * G_STAGE * (int)sizeof(float))   // 2 stages = 73728 B

__global__ __launch_bounds__(256, 2) void tf32_gemm(
    const float* __restrict__ A, const float* __restrict__ W,
    float* __restrict__ Cout, int M, int N, int K)
{
    extern __shared__ float sm[];
    const int tid  = threadIdx.x;
    const int lane = tid & 31;
    const int wid  = tid >> 5;
    const int wm   = wid >> 2;          // 0..1  (m 64-blocks)
    const int wn   = wid & 3;           // 0..3  (n 32-blocks)
    const int g    = lane >> 2;         // group id (rows / n-cols)
    const int t    = lane & 3;          // thread in group (k-cols)
    const int row0 = blockIdx.y << 7;
    const int col0 = blockIdx.x << 7;

    float acc[4][4][4];
    #pragma unroll
    for (int i = 0; i < 4; ++i)
        #pragma unroll
        for (int j = 0; j < 4; ++j)
            #pragma unroll
            for (int r = 0; r < 4; ++r) acc[i][j][r] = 0.f;

    // copy task decomposition: 1024 float4 per matrix per chunk, 4 per thread
    const int cr = tid >> 3;            // base row (advances by 32 per pass)
    const int cc = (tid & 7) << 2;      // k offset (0,4,...,28)

    const int nchunk = K / GK;

    // ---- issue chunk 0 ----
    {
        float* as = sm;                 // stage 0
        float* bs = sm + G_TILE;
        #pragma unroll
        for (int it = 0; it < 4; ++it) {
            int r = cr + (it << 5);
            cp_async16(smem_u32(as + r * GSTRIDE + cc),
                       A + (size_t)(row0 + r) * K + cc);
            cp_async16(smem_u32(bs + r * GSTRIDE + cc),
                       W + (size_t)(col0 + r) * K + cc);
        }
        cp_commit();
    }

    for (int i = 0; i < nchunk; ++i) {
        if (i + 1 < nchunk) {
            float* as = sm + ((i + 1) & 1) * G_STAGE;
            float* bs = as + G_TILE;
            const int k0 = (i + 1) * GK;
            #pragma unroll
            for (int it = 0; it < 4; ++it) {
                int r = cr + (it << 5);
                cp_async16(smem_u32(as + r * GSTRIDE + cc + 0) - (cc & 0),  // keep form
                           A + (size_t)(row0 + r) * K + k0 + cc);
                cp_async16(smem_u32(bs + r * GSTRIDE + cc),
                           W + (size_t)(col0 + r) * K + k0 + cc);
            }
            cp_commit();
            cp_wait<1>();
        } else {
            cp_wait<0>();
        }
        __syncthreads();

        const float* as = sm + (i & 1) * G_STAGE + wm * 64 * GSTRIDE;
        const float* bs = sm + (i & 1) * G_STAGE + G_TILE + wn * 32 * GSTRIDE;

        #pragma unroll
        for (int ks = 0; ks < 4; ++ks) {
            uint32_t af[4][4];
            #pragma unroll
            for (int mt = 0; mt < 4; ++mt) {
                const uint32_t* ap =
                    (const uint32_t*)(as + (mt * 16 + g) * GSTRIDE + ks * 8 + t);
                af[mt][0] = ap[0];
                af[mt][1] = ap[8 * GSTRIDE];
                af[mt][2] = ap[4];
                af[mt][3] = ap[8 * GSTRIDE + 4];
            }
            uint32_t bf[4][2];
            #pragma unroll
            for (int nt = 0; nt < 4; ++nt) {
                const uint32_t* bp =
                    (const uint32_t*)(bs + (nt * 8 + g) * GSTRIDE + ks * 8 + t);
                bf[nt][0] = bp[0];
                bf[nt][1] = bp[4];
            }
            #pragma unroll
            for (int mt = 0; mt < 4; ++mt)
                #pragma unroll
                for (int nt = 0; nt < 4; ++nt)
                    mma_tf32(acc[mt][nt], af[mt], bf[nt]);
        }
        __syncthreads();
    }

    // Epilogue: c0,c1 -> (row g, col 2t,2t+1); c2,c3 -> (row g+8)
    #pragma unroll
    for (int mt = 0; mt < 4; ++mt) {
        #pragma unroll
        for (int nt = 0; nt < 4; ++nt) {
            int row = row0 + wm * 64 + mt * 16 + g;
            int col = col0 + wn * 32 + nt * 8 + 2 * t;
            *(float2*)(Cout + (size_t)row * N + col) =
                make_float2(acc[mt][nt][0], acc[mt][nt][1]);
            *(float2*)(Cout + (size_t)(row + 8) * N + col) =
                make_float2(acc[mt][nt][2], acc[mt][nt][3]);
        }
    }
}

// ===========================================================================
// Round fp32 -> nearest-tf32 (kills truncation bias in the tensor path)
// ===========================================================================
__device__ __forceinline__ float rtf32(float a) {
    float r;
    asm("cvt.rna.tf32.f32 %0, %1;" : "=f"(r) : "f"(a));
    return r;
}
__global__ void tf32_round_kernel(const float4* __restrict__ in,
                                  float4* __restrict__ out, int n4)
{
    int i = blockIdx.x * blockDim.x + threadIdx.x;
    if (i >= n4) return;
    float4 v = in[i];
    v.x = rtf32(v.x); v.y = rtf32(v.y); v.z = rtf32(v.z); v.w = rtf32(v.w);
    out[i] = v;
}

// ---------------------------------------------------------------------------
// RoPE in-place on Q and K (unchanged)
// ---------------------------------------------------------------------------
__global__ void rope_kernel(float* __restrict__ q, float* __restrict__ k)
{
    int idx = blockIdx.x * blockDim.x + threadIdx.x;
    int i = idx & 31;
    int h = (idx >> 5) & 15;
    int t = (idx >> 9) & 2047;
    int b = idx >> 20;

    float inv = powf(10000.0f, -(float)(2 * i) / (float)D_);
    float ang = (float)t * inv;
    float s, c;
    sincosf(ang, &s, &c);

    size_t base = ((size_t)(b * T_ + t)) * C_ + h * D_ + i;
    float x1 = q[base], x2 = q[base + 32];
    q[base]      = x1 * c - x2 * s;
    q[base + 32] = x2 * c + x1 * s;
    x1 = k[base]; x2 = k[base + 32];
    k[base]      = x1 * c - x2 * s;
    k[base + 32] = x2 * c + x1 * s;
}

// ---------------------------------------------------------------------------
// Causal flash attention, fp32 SIMT (unchanged; tensorize next round)
// ---------------------------------------------------------------------------
#define FA_PAD 65
#define FA_SMEM (3 * 64 * FA_PAD * (int)sizeof(float))

__global__ __launch_bounds__(256) void flash_attn(
    const float* __restrict__ q, const float* __restrict__ k,
    const float* __restrict__ v, float* __restrict__ o)
{
    extern __shared__ float sm[];
    float* Qs  = sm;
    float* KPs = sm + 64 * FA_PAD;
    float* Vs  = sm + 2 * 64 * FA_PAD;

    const int tid = threadIdx.x;
    const int tx = tid & 15;
    const int ty = tid >> 4;
    const int qblk = blockIdx.x;
    const int bh = blockIdx.y;
    const int b = bh >> 4, h = bh & 15;
    const int i0 = qblk << 6;

    const float* qb = q + ((size_t)b * T_) * C_ + h * D_;
    const float* kb = k + ((size_t)b * T_) * C_ + h * D_;
    const float* vb = v + ((size_t)b * T_) * C_ + h * D_;

    for (int idx = tid; idx < 64 * 64; idx += 256) {
        int r = idx >> 6, c = idx & 63;
        Qs[r * FA_PAD + c] = qb[(size_t)(i0 + r) * C_ + c];
    }

    float acc[4][4];
    float m_i[4], l_i[4];
    #pragma unroll
    for (int i = 0; i < 4; ++i) {
        m_i[i] = -1e30f; l_i[i] = 0.f;
        #pragma unroll
        for (int j = 0; j < 4; ++j) acc[i][j] = 0.f;
    }
    const int r0 = ty << 2, c0 = tx << 2;
    __syncthreads();

    for (int j = 0; j <= qblk; ++j) {
        for (int idx = tid; idx < 64 * 64; idx += 256) {
            int r = idx >> 6, c = idx & 63;
            KPs[r * FA_PAD + c] = kb[(size_t)((j << 6) + r) * C_ + c];
            Vs [r * FA_PAD + c] = vb[(size_t)((j << 6) + r) * C_ + c];
        }
        __syncthreads();

        float s[4][4];
        #pragma unroll
        for (int i = 0; i < 4; ++i)
            #pragma unroll
            for (int jj = 0; jj < 4; ++jj) s[i][jj] = 0.f;

        #pragma unroll 8
        for (int kk = 0; kk < 64; ++kk) {
            float qv[4], kv[4];
            #pragma unroll
            for (int i = 0; i < 4; ++i) qv[i] = Qs[(r0 + i) * FA_PAD + kk];
            #pragma unroll
            for (int i = 0; i < 4; ++i) kv[i] = KPs[(c0 + i) * FA_PAD + kk];
            #pragma unroll
            for (int i = 0; i < 4; ++i)
                #pragma unroll
                for (int jj = 0; jj < 4; ++jj)
                    s[i][jj] += qv[i] * kv[jj];
        }
        __syncthreads();

        #pragma unroll
        for (int i = 0; i < 4; ++i) {
            int grow = i0 + r0 + i;
            float sv[4];
            float mx = -1e30f;
            #pragma unroll
            for (int jj = 0; jj < 4; ++jj) {
                int gcol = (j << 6) + c0 + jj;
                float val = s[i][jj] * 0.125f;
                if (gcol > grow) val = -1e30f;
                sv[jj] = val;
                mx = fmaxf(mx, val);
            }
            #pragma unroll
            for (int off = 1; off < 16; off <<= 1)
                mx = fmaxf(mx, __shfl_xor_sync(0xffffffffu, mx, off));
            float m_new = fmaxf(m_i[i], mx);
            float scale = __expf(m_i[i] - m_new);
            float rs = 0.f;
            #pragma unroll
            for (int jj = 0; jj < 4; ++jj) {
                float p = __expf(sv[jj] - m_new);
                sv[jj] = p;
                rs += p;
            }
            #pragma unroll
            for (int off = 1; off < 16; off <<= 1)
                rs += __shfl_xor_sync(0xffffffffu, rs, off);
            l_i[i] = l_i[i] * scale + rs;
            m_i[i] = m_new;
            #pragma unroll
            for (int jj = 0; jj < 4; ++jj) acc[i][jj] *= scale;
            #pragma unroll
            for (int jj = 0; jj < 4; ++jj)
                KPs[(r0 + i) * FA_PAD + c0 + jj] = sv[jj];
        }
        __syncthreads();

        #pragma unroll 8
        for (int ss = 0; ss < 64; ++ss) {
            float pv[4], vv[4];
            #pragma unroll
            for (int i = 0; i < 4; ++i) pv[i] = KPs[(r0 + i) * FA_PAD + ss];
            #pragma unroll
            for (int jj = 0; jj < 4; ++jj) vv[jj] = Vs[ss * FA_PAD + c0 + jj];
            #pragma unroll
            for (int i = 0; i < 4; ++i)
                #pragma unroll
                for (int jj = 0; jj < 4; ++jj)
                    acc[i][jj] += pv[i] * vv[jj];
        }
        __syncthreads();
    }

    float* ob = o + ((size_t)b * T_) * C_ + h * D_;
    #pragma unroll
    for (int i = 0; i < 4; ++i) {
        float inv_l = 1.f / l_i[i];
        #pragma unroll
        for (int jj = 0; jj < 4; ++jj)
            ob[(size_t)(i0 + r0 + i) * C_ + c0 + jj] = acc[i][jj] * inv_l;
    }
}

// ---------------------------------------------------------------------------
// Launch
// ---------------------------------------------------------------------------
extern "C" void kernel_launch(void* const* d_in, const int* in_sizes, int n_in,
                              void* d_out, int out_size)
{
    const float* x  = (const float*)d_in[0];
    const float* Wq = (const float*)d_in[1];
    const float* Wk = (const float*)d_in[2];
    const float* Wv = (const float*)d_in[3];
    const float* Wo = (const float*)d_in[4];
    float* out = (float*)d_out;

    float *qp, *kp, *vp, *ap, *xr, *wq, *wk, *wv, *wo;
    cudaGetSymbolAddress((void**)&qp, g_q);
    cudaGetSymbolAddress((void**)&kp, g_k);
    cudaGetSymbolAddress((void**)&vp, g_v);
    cudaGetSymbolAddress((void**)&ap, g_attn);
    cudaGetSymbolAddress((void**)&xr, g_xr);
    cudaGetSymbolAddress((void**)&wq, g_wq);
    cudaGetSymbolAddress((void**)&wk, g_wk);
    cudaGetSymbolAddress((void**)&wv, g_wv);
    cudaGetSymbolAddress((void**)&wo, g_wo);

    cudaFuncSetAttribute((const void*)tf32_gemm,
                         cudaFuncAttributeMaxDynamicSharedMemorySize, G_SMEM);
    cudaFuncSetAttribute((const void*)flash_attn,
                         cudaFuncAttributeMaxDynamicSharedMemorySize, FA_SMEM);

    // Round operands to nearest-tf32
    int n4x = BT_ * C_ / 4, n4w = C_ * C_ / 4;
    tf32_round_kernel<<<n4x / 256, 256>>>((const float4*)x,  (float4*)xr, n4x);
    tf32_round_kernel<<<n4w / 256, 256>>>((const float4*)Wq, (float4*)wq, n4w);
    tf32_round_kernel<<<n4w / 256, 256>>>((const float4*)Wk, (float4*)wk, n4w);
    tf32_round_kernel<<<n4w / 256, 256>>>((const float4*)Wv, (float4*)wv, n4w);
    tf32_round_kernel<<<n4w / 256, 256>>>((const float4*)Wo, (float4*)wo, n4w);

    dim3 gg(C_ / 128, BT_ / 128);   // (8, 32)
    tf32_gemm<<<gg, 256, G_SMEM>>>(xr, wq, qp, BT_, C_, C_);
    tf32_gemm<<<gg, 256, G_SMEM>>>(xr, wk, kp, BT_, C_, C_);
    tf32_gemm<<<gg, 256, G_SMEM>>>(xr, wv, vp, BT_, C_, C_);

    rope_kernel<<<(B_ * T_ * H_ * (D_ / 2)) / 256, 256>>>(qp, kp);

    flash_attn<<<dim3(T_ / 64, B_ * H_), 256, FA_SMEM>>>(qp, kp, vp, ap);

    // Round attention output, then final projection
    tf32_round_kernel<<<n4x / 256, 256>>>((const float4*)ap, (float4*)ap, n4x);
    tf32_gemm<<<gg, 256, G_SMEM>>>(ap, wo, out, BT_, C_, C_);
}

// round 6
// speedup vs baseline: 2.1025x; 1.1796x over previous
#include <cuda_runtime.h>
#include <math.h>
#include <stdint.h>

// Problem constants (fixed by setup_inputs)
#define B_  2
#define T_  2048
#define C_  1024
#define H_  16
#define D_  64
#define BT_ (B_*T_)          // 4096

// Scratch (allocation-free rule: __device__ globals)
__device__ float g_q[BT_*C_];
__device__ float g_k[BT_*C_];
__device__ float g_v[BT_*C_];
__device__ float g_attn[BT_*C_];
__device__ float g_xr[BT_*C_];      // tf32-rounded x
__device__ float g_wq[C_*C_];
__device__ float g_wk[C_*C_];
__device__ float g_wv[C_*C_];
__device__ float g_wo[C_*C_];

// ===========================================================================
// Helpers
// ===========================================================================
__device__ __forceinline__ uint32_t smem_u32(const void* p) {
    uint32_t a;
    asm("{ .reg .u64 t; cvta.to.shared.u64 t, %1; cvt.u32.u64 %0, t; }"
        : "=r"(a) : "l"(p));
    return a;
}
__device__ __forceinline__ void cp_async16(uint32_t saddr, const void* gaddr) {
    asm volatile("cp.async.ca.shared.global [%0], [%1], 16;"
                 :: "r"(saddr), "l"(gaddr) : "memory");
}
__device__ __forceinline__ void cp_commit() {
    asm volatile("cp.async.commit_group;" ::: "memory");
}
template<int N>
__device__ __forceinline__ void cp_wait() {
    asm volatile("cp.async.wait_group %0;" :: "n"(N) : "memory");
}
// tf32 mma: D = A(16x8) * B(8x8) + D   (row.col)
__device__ __forceinline__ void mma_tf32(float* c, const uint32_t* a, const uint32_t* b) {
    asm volatile(
        "mma.sync.aligned.m16n8k8.row.col.f32.tf32.tf32.f32 "
        "{%0,%1,%2,%3}, {%4,%5,%6,%7}, {%8,%9}, {%0,%1,%2,%3};"
        : "+f"(c[0]), "+f"(c[1]), "+f"(c[2]), "+f"(c[3])
        : "r"(a[0]), "r"(a[1]), "r"(a[2]), "r"(a[3]), "r"(b[0]), "r"(b[1]));
}
__device__ __forceinline__ float rtf32(float a) {
    float r;
    asm("cvt.rna.tf32.f32 %0, %1;" : "=f"(r) : "f"(a));
    return r;
}
__device__ __forceinline__ void split1(float x, uint32_t& hi, uint32_t& lo) {
    float h = rtf32(x);
    hi = __float_as_uint(h);
    lo = __float_as_uint(rtf32(x - h));
}

// ===========================================================================
// tf32 tensor-core GEMM (NT): C[m,n] = sum_k A[m,k] * W[n,k]
// (unchanged from R5 — validated)
// ===========================================================================
#define GK      32
#define GSTRIDE 36
#define G_TILE  (128 * GSTRIDE)
#define G_STAGE (2 * G_TILE)
#define G_SMEM  (2 * G_STAGE * (int)sizeof(float))

__global__ __launch_bounds__(256, 2) void tf32_gemm(
    const float* __restrict__ A, const float* __restrict__ W,
    float* __restrict__ Cout, int M, int N, int K)
{
    extern __shared__ float sm[];
    const int tid  = threadIdx.x;
    const int lane = tid & 31;
    const int wid  = tid >> 5;
    const int wm   = wid >> 2;
    const int wn   = wid & 3;
    const int g    = lane >> 2;
    const int t    = lane & 3;
    const int row0 = blockIdx.y << 7;
    const int col0 = blockIdx.x << 7;

    float acc[4][4][4];
    #pragma unroll
    for (int i = 0; i < 4; ++i)
        #pragma unroll
        for (int j = 0; j < 4; ++j)
            #pragma unroll
            for (int r = 0; r < 4; ++r) acc[i][j][r] = 0.f;

    const int cr = tid >> 3;
    const int cc = (tid & 7) << 2;
    const int nchunk = K / GK;

    {
        float* as = sm;
        float* bs = sm + G_TILE;
        #pragma unroll
        for (int it = 0; it < 4; ++it) {
            int r = cr + (it << 5);
            cp_async16(smem_u32(as + r * GSTRIDE + cc),
                       A + (size_t)(row0 + r) * K + cc);
            cp_async16(smem_u32(bs + r * GSTRIDE + cc),
                       W + (size_t)(col0 + r) * K + cc);
        }
        cp_commit();
    }

    for (int i = 0; i < nchunk; ++i) {
        if (i + 1 < nchunk) {
            float* as = sm + ((i + 1) & 1) * G_STAGE;
            float* bs = as + G_TILE;
            const int k0 = (i + 1) * GK;
            #pragma unroll
            for (int it = 0; it < 4; ++it) {
                int r = cr + (it << 5);
                cp_async16(smem_u32(as + r * GSTRIDE + cc),
                           A + (size_t)(row0 + r) * K + k0 + cc);
                cp_async16(smem_u32(bs + r * GSTRIDE + cc),
                           W + (size_t)(col0 + r) * K + k0 + cc);
            }
            cp_commit();
            cp_wait<1>();
        } else {
            cp_wait<0>();
        }
        __syncthreads();

        const float* as = sm + (i & 1) * G_STAGE + wm * 64 * GSTRIDE;
        const float* bs = sm + (i & 1) * G_STAGE + G_TILE + wn * 32 * GSTRIDE;

        #pragma unroll
        for (int ks = 0; ks < 4; ++ks) {
            uint32_t af[4][4];
            #pragma unroll
            for (int mt = 0; mt < 4; ++mt) {
                const uint32_t* ap =
                    (const uint32_t*)(as + (mt * 16 + g) * GSTRIDE + ks * 8 + t);
                af[mt][0] = ap[0];
                af[mt][1] = ap[8 * GSTRIDE];
                af[mt][2] = ap[4];
                af[mt][3] = ap[8 * GSTRIDE + 4];
            }
            uint32_t bf[4][2];
            #pragma unroll
            for (int nt = 0; nt < 4; ++nt) {
                const uint32_t* bp =
                    (const uint32_t*)(bs + (nt * 8 + g) * GSTRIDE + ks * 8 + t);
                bf[nt][0] = bp[0];
                bf[nt][1] = bp[4];
            }
            #pragma unroll
            for (int mt = 0; mt < 4; ++mt)
                #pragma unroll
                for (int nt = 0; nt < 4; ++nt)
                    mma_tf32(acc[mt][nt], af[mt], bf[nt]);
        }
        __syncthreads();
    }

    #pragma unroll
    for (int mt = 0; mt < 4; ++mt) {
        #pragma unroll
        for (int nt = 0; nt < 4; ++nt) {
            int row = row0 + wm * 64 + mt * 16 + g;
            int col = col0 + wn * 32 + nt * 8 + 2 * t;
            *(float2*)(Cout + (size_t)row * N + col) =
                make_float2(acc[mt][nt][0], acc[mt][nt][1]);
            *(float2*)(Cout + (size_t)(row + 8) * N + col) =
                make_float2(acc[mt][nt][2], acc[mt][nt][3]);
        }
    }
}

// ===========================================================================
// Round fp32 -> nearest-tf32
// ===========================================================================
__global__ void tf32_round_kernel(const float4* __restrict__ in,
                                  float4* __restrict__ out, int n4)
{
    int i = blockIdx.x * blockDim.x + threadIdx.x;
    if (i >= n4) return;
    float4 v = in[i];
    v.x = rtf32(v.x); v.y = rtf32(v.y); v.z = rtf32(v.z); v.w = rtf32(v.w);
    out[i] = v;
}

// ---------------------------------------------------------------------------
// RoPE in-place on Q and K (unchanged)
// ---------------------------------------------------------------------------
__global__ void rope_kernel(float* __restrict__ q, float* __restrict__ k)
{
    int idx = blockIdx.x * blockDim.x + threadIdx.x;
    int i = idx & 31;
    int h = (idx >> 5) & 15;
    int t = (idx >> 9) & 2047;
    int b = idx >> 20;

    float inv = powf(10000.0f, -(float)(2 * i) / (float)D_);
    float ang = (float)t * inv;
    float s, c;
    sincosf(ang, &s, &c);

    size_t base = ((size_t)(b * T_ + t)) * C_ + h * D_ + i;
    float x1 = q[base], x2 = q[base + 32];
    q[base]      = x1 * c - x2 * s;
    q[base + 32] = x2 * c + x1 * s;
    x1 = k[base]; x2 = k[base + 32];
    k[base]      = x1 * c - x2 * s;
    k[base + 32] = x2 * c + x1 * s;
}

// ===========================================================================
// Tensor-core causal flash attention (tf32x3, near-fp32 precision).
// Tile: 128 queries x 64 keys. 256 threads; warp w owns query rows
// [w*16, w*16+16). m16n8k8 tf32 MMAs; hi/lo splits computed at fragment load.
// Smem strides padded so all fragment LDS patterns are bank-conflict-free.
// Output written pre-rounded to tf32 (feeds the Wo GEMM directly).
// ===========================================================================
#define FQ   128
#define FK   64
#define QSTR 68
#define KSTR 68
#define VSTR 72
#define PSTR 68
#define FA2_Q 0
#define FA2_K (FQ*QSTR)                       // 8704
#define FA2_V (FA2_K + FK*KSTR)               // 13056
#define FA2_P (FA2_V + FK*VSTR)               // 17664
#define FA2_SMEM ((FA2_P + FQ*PSTR) * (int)sizeof(float))   // 105472 B

__global__ __launch_bounds__(256) void flash_attn_tc(
    const float* __restrict__ q, const float* __restrict__ k,
    const float* __restrict__ v, float* __restrict__ o)
{
    extern __shared__ float sm[];
    float* Qs = sm + FA2_Q;
    float* Ks = sm + FA2_K;
    float* Vs = sm + FA2_V;
    float* Ps = sm + FA2_P;

    const int tid  = threadIdx.x;
    const int lane = tid & 31;
    const int w    = tid >> 5;
    const int g    = lane >> 2;
    const int t    = lane & 3;
    const int qb   = blockIdx.x;
    const int bh   = blockIdx.y;
    const int b    = bh >> 4, h = bh & 15;
    const int i0   = qb << 7;

    const float* qbp = q + (size_t)b * T_ * C_ + h * D_;
    const float* kbp = k + (size_t)b * T_ * C_ + h * D_;
    const float* vbp = v + (size_t)b * T_ * C_ + h * D_;

    // Load Q tile (128 x 64) via cp.async
    #pragma unroll
    for (int it = 0; it < 8; ++it) {
        int task = tid + (it << 8);
        int r = task >> 4, c = (task & 15) << 2;
        cp_async16(smem_u32(Qs + r * QSTR + c),
                   qbp + (size_t)(i0 + r) * C_ + c);
    }
    cp_commit();

    float oacc[8][4];
    #pragma unroll
    for (int nt = 0; nt < 8; ++nt)
        #pragma unroll
        for (int e = 0; e < 4; ++e) oacc[nt][e] = 0.f;
    float m0 = -1e30f, m1 = -1e30f, l0 = 0.f, l1 = 0.f;

    const int grow0 = i0 + w * 16 + g;      // thread's low row
    const int njt = (i0 >> 6) + 2;          // key tiles needed (causal)

    for (int j = 0; j < njt; ++j) {
        __syncthreads();                    // prev iter done reading K/V
        #pragma unroll
        for (int it = 0; it < 4; ++it) {
            int task = tid + (it << 8);
            int r = task >> 4, c = (task & 15) << 2;
            cp_async16(smem_u32(Ks + r * KSTR + c),
                       kbp + (size_t)((j << 6) + r) * C_ + c);
            cp_async16(smem_u32(Vs + r * VSTR + c),
                       vbp + (size_t)((j << 6) + r) * C_ + c);
        }
        cp_commit();
        cp_wait<0>();                       // also covers the Q load on j==0
        __syncthreads();

        // ---- S = Q K^T  (tf32x3) ----
        float sacc[8][4];
        #pragma unroll
        for (int nt = 0; nt < 8; ++nt)
            #pragma unroll
            for (int e = 0; e < 4; ++e) sacc[nt][e] = 0.f;

        const float* qrow = Qs + (w * 16 + g) * QSTR;
        #pragma unroll
        for (int ks = 0; ks < 8; ++ks) {
            uint32_t ah[4], al[4];
            split1(qrow[ks * 8 + t],            ah[0], al[0]);
            split1(qrow[8 * QSTR + ks * 8 + t], ah[1], al[1]);
            split1(qrow[ks * 8 + t + 4],            ah[2], al[2]);
            split1(qrow[8 * QSTR + ks * 8 + t + 4], ah[3], al[3]);
            #pragma unroll
            for (int nt = 0; nt < 8; ++nt) {
                const float* krow = Ks + (nt * 8 + g) * KSTR + ks * 8;
                uint32_t bh2[2], bl2[2];
                split1(krow[t],     bh2[0], bl2[0]);
                split1(krow[t + 4], bh2[1], bl2[1]);
                mma_tf32(sacc[nt], ah, bh2);
                mma_tf32(sacc[nt], ah, bl2);
                mma_tf32(sacc[nt], al, bh2);
            }
        }

        // ---- online softmax (rows grow0 and grow0+8) ----
        const int colj = j << 6;
        float mx0 = -1e30f, mx1 = -1e30f;
        #pragma unroll
        for (int nt = 0; nt < 8; ++nt) {
            #pragma unroll
            for (int e = 0; e < 4; ++e) {
                int gcol = colj + nt * 8 + 2 * t + (e & 1);
                int grow = (e < 2) ? grow0 : grow0 + 8;
                float val = sacc[nt][e] * 0.125f;
                if (gcol > grow) val = -1e30f;
                sacc[nt][e] = val;
            }
            mx0 = fmaxf(mx0, fmaxf(sacc[nt][0], sacc[nt][1]));
            mx1 = fmaxf(mx1, fmaxf(sacc[nt][2], sacc[nt][3]));
        }
        mx0 = fmaxf(mx0, __shfl_xor_sync(0xffffffffu, mx0, 1));
        mx0 = fmaxf(mx0, __shfl_xor_sync(0xffffffffu, mx0, 2));
        mx1 = fmaxf(mx1, __shfl_xor_sync(0xffffffffu, mx1, 1));
        mx1 = fmaxf(mx1, __shfl_xor_sync(0xffffffffu, mx1, 2));

        float mn0 = fmaxf(m0, mx0), mn1 = fmaxf(m1, mx1);
        float sc0 = __expf(m0 - mn0), sc1 = __expf(m1 - mn1);
        float rs0 = 0.f, rs1 = 0.f;
        #pragma unroll
        for (int nt = 0; nt < 8; ++nt) {
            float p0 = __expf(sacc[nt][0] - mn0);
            float p1 = __expf(sacc[nt][1] - mn0);
            float p2 = __expf(sacc[nt][2] - mn1);
            float p3 = __expf(sacc[nt][3] - mn1);
            sacc[nt][0] = p0; sacc[nt][1] = p1;
            sacc[nt][2] = p2; sacc[nt][3] = p3;
            rs0 += p0 + p1; rs1 += p2 + p3;
        }
        rs0 += __shfl_xor_sync(0xffffffffu, rs0, 1);
        rs0 += __shfl_xor_sync(0xffffffffu, rs0, 2);
        rs1 += __shfl_xor_sync(0xffffffffu, rs1, 1);
        rs1 += __shfl_xor_sync(0xffffffffu, rs1, 2);
        l0 = l0 * sc0 + rs0; m0 = mn0;
        l1 = l1 * sc1 + rs1; m1 = mn1;
        #pragma unroll
        for (int nt = 0; nt < 8; ++nt) {
            oacc[nt][0] *= sc0; oacc[nt][1] *= sc0;
            oacc[nt][2] *= sc1; oacc[nt][3] *= sc1;
        }

        // ---- write P (warp-private rows) ----
        __syncwarp();                      // prev PV reads done
        float* prow = Ps + (w * 16 + g) * PSTR;
        #pragma unroll
        for (int nt = 0; nt < 8; ++nt) {
            *(float2*)(prow + nt * 8 + 2 * t) =
                make_float2(sacc[nt][0], sacc[nt][1]);
            *(float2*)(prow + 8 * PSTR + nt * 8 + 2 * t) =
                make_float2(sacc[nt][2], sacc[nt][3]);
        }
        __syncwarp();                      // P visible to whole warp

        // ---- O += P V  (tf32x3) ----
        #pragma unroll
        for (int ks = 0; ks < 8; ++ks) {
            uint32_t ah[4], al[4];
            split1(prow[ks * 8 + t],            ah[0], al[0]);
            split1(prow[8 * PSTR + ks * 8 + t], ah[1], al[1]);
            split1(prow[ks * 8 + t + 4],            ah[2], al[2]);
            split1(prow[8 * PSTR + ks * 8 + t + 4], ah[3], al[3]);
            #pragma unroll
            for (int nt = 0; nt < 8; ++nt) {
                uint32_t bh2[2], bl2[2];
                split1(Vs[(ks * 8 + t) * VSTR + nt * 8 + g],     bh2[0], bl2[0]);
                split1(Vs[(ks * 8 + t + 4) * VSTR + nt * 8 + g], bh2[1], bl2[1]);
                mma_tf32(oacc[nt], ah, bh2);
                mma_tf32(oacc[nt], ah, bl2);
                mma_tf32(oacc[nt], al, bh2);
            }
        }
    }

    // ---- epilogue (pre-rounded to tf32 for the Wo GEMM) ----
    float iv0 = 1.f / l0, iv1 = 1.f / l1;
    float* ob = o + (size_t)b * T_ * C_ + h * D_;
    #pragma unroll
    for (int nt = 0; nt < 8; ++nt) {
        int col = nt * 8 + 2 * t;
        *(float2*)(ob + (size_t)grow0 * C_ + col) =
            make_float2(rtf32(oacc[nt][0] * iv0), rtf32(oacc[nt][1] * iv0));
        *(float2*)(ob + (size_t)(grow0 + 8) * C_ + col) =
            make_float2(rtf32(oacc[nt][2] * iv1), rtf32(oacc[nt][3] * iv1));
    }
}

// ---------------------------------------------------------------------------
// Launch
// ---------------------------------------------------------------------------
extern "C" void kernel_launch(void* const* d_in, const int* in_sizes, int n_in,
                              void* d_out, int out_size)
{
    const float* x  = (const float*)d_in[0];
    const float* Wq = (const float*)d_in[1];
    const float* Wk = (const float*)d_in[2];
    const float* Wv = (const float*)d_in[3];
    const float* Wo = (const float*)d_in[4];
    float* out = (float*)d_out;

    float *qp, *kp, *vp, *ap, *xr, *wq, *wk, *wv, *wo;
    cudaGetSymbolAddress((void**)&qp, g_q);
    cudaGetSymbolAddress((void**)&kp, g_k);
    cudaGetSymbolAddress((void**)&vp, g_v);
    cudaGetSymbolAddress((void**)&ap, g_attn);
    cudaGetSymbolAddress((void**)&xr, g_xr);
    cudaGetSymbolAddress((void**)&wq, g_wq);
    cudaGetSymbolAddress((void**)&wk, g_wk);
    cudaGetSymbolAddress((void**)&wv, g_wv);
    cudaGetSymbolAddress((void**)&wo, g_wo);

    cudaFuncSetAttribute((const void*)tf32_gemm,
                         cudaFuncAttributeMaxDynamicSharedMemorySize, G_SMEM);
    cudaFuncSetAttribute((const void*)flash_attn_tc,
                         cudaFuncAttributeMaxDynamicSharedMemorySize, FA2_SMEM);

    // Round GEMM operands to nearest-tf32
    int n4x = BT_ * C_ / 4, n4w = C_ * C_ / 4;
    tf32_round_kernel<<<n4x / 256, 256>>>((const float4*)x,  (float4*)xr, n4x);
    tf32_round_kernel<<<n4w / 256, 256>>>((const float4*)Wq, (float4*)wq, n4w);
    tf32_round_kernel<<<n4w / 256, 256>>>((const float4*)Wk, (float4*)wk, n4w);
    tf32_round_kernel<<<n4w / 256, 256>>>((const float4*)Wv, (float4*)wv, n4w);
    tf32_round_kernel<<<n4w / 256, 256>>>((const float4*)Wo, (float4*)wo, n4w);

    dim3 gg(C_ / 128, BT_ / 128);   // (8, 32)
    tf32_gemm<<<gg, 256, G_SMEM>>>(xr, wq, qp, BT_, C_, C_);
    tf32_gemm<<<gg, 256, G_SMEM>>>(xr, wk, kp, BT_, C_, C_);
    tf32_gemm<<<gg, 256, G_SMEM>>>(xr, wv, vp, BT_, C_, C_);

    rope_kernel<<<(B_ * T_ * H_ * (D_ / 2)) / 256, 256>>>(qp, kp);

    flash_attn_tc<<<dim3(T_ / 128, B_ * H_), 256, FA2_SMEM>>>(qp, kp, vp, ap);

    tf32_gemm<<<gg, 256, G_SMEM>>>(ap, wo, out, BT_, C_, C_);
}